// round 2
// baseline (speedup 1.0000x reference)
#include <cuda_runtime.h>
#include <math.h>

#define PIX 25088           // 8*56*56
#define NWIN 392            // 8*49
#define CH 256

// ---------------- scratch (device globals; no allocation allowed) ----------------
__device__ float g_xn  [PIX*CH];      // LN1 output, window-major
__device__ float g_qkv [PIX*768];     // qkv, window-major rows
__device__ float g_qwin[NWIN*256];
__device__ float g_kwin[NWIN*256];
__device__ int   g_ridx[NWIN*4];
__device__ float g_lepe[PIX*CH];      // window-major
__device__ float g_attn[PIX*CH];      // window-major
__device__ float g_x2  [PIX*CH];      // image-major (x + bra)
__device__ float g_ln2 [PIX*CH];      // image-major
__device__ float g_hid [PIX*1024];    // image-major

// window <-> image row maps
__device__ __forceinline__ int img2win(int pix){
    int n = pix / 3136, r = pix % 3136;
    int y = r / 56, x = r % 56;
    return (n*49 + (y>>3)*7 + (x>>3))*64 + ((y&7)<<3) + (x&7);
}
__device__ __forceinline__ int win2img(int rw){
    int n = rw / 3136, r = rw % 3136;
    int p = r >> 6, q = r & 63;
    int y = ((p/7)<<3) + (q>>3), x = ((p%7)<<3) + (q&7);
    return n*3136 + y*56 + x;
}

// ---------------- LayerNorm: one warp per pixel ----------------
template<bool REMAP>
__global__ void ln_kernel(const float* __restrict__ in, const float* __restrict__ g,
                          const float* __restrict__ b, float* __restrict__ out){
    int warp = threadIdx.x >> 5, lane = threadIdx.x & 31;
    int pix = blockIdx.x * 8 + warp;
    const float* row = in + (size_t)pix * CH;
    int c0 = lane * 8;
    float4 v0 = *(const float4*)(row + c0);
    float4 v1 = *(const float4*)(row + c0 + 4);
    float vals[8] = {v0.x,v0.y,v0.z,v0.w,v1.x,v1.y,v1.z,v1.w};
    float s = 0.f, ss = 0.f;
    #pragma unroll
    for (int u = 0; u < 8; u++){ s += vals[u]; ss += vals[u]*vals[u]; }
    #pragma unroll
    for (int o = 16; o; o >>= 1){
        s  += __shfl_xor_sync(0xffffffffu, s,  o);
        ss += __shfl_xor_sync(0xffffffffu, ss, o);
    }
    float mu  = s  * (1.f/256.f);
    float var = ss * (1.f/256.f) - mu*mu;
    float inv = rsqrtf(var + 1e-6f);
    int orow = REMAP ? img2win(pix) : pix;
    float* op = out + (size_t)orow * CH + c0;
    #pragma unroll
    for (int u = 0; u < 8; u++)
        op[u] = (vals[u] - mu) * inv * g[c0+u] + b[c0+u];
}

// ---------------- window means of q and k ----------------
__global__ void win_mean_kernel(){
    int wb = blockIdx.x;          // 0..391
    int c  = threadIdx.x;         // 0..255
    const float* base = g_qkv + (size_t)wb * 64 * 768;
    float sq = 0.f, sk = 0.f;
    #pragma unroll 4
    for (int r = 0; r < 64; r++){
        sq += base[r*768 + c];
        sk += base[r*768 + 256 + c];
    }
    g_qwin[wb*256 + c] = sq * (1.f/64.f);
    g_kwin[wb*256 + c] = sk * (1.f/64.f);
}

// ---------------- routing logits + top-4 (one block per batch) ----------------
__global__ void logit_topk_kernel(){
    int n = blockIdx.x;
    int tid = threadIdx.x;
    extern __shared__ float sm[];
    float* qw = sm;                 // 49*257
    float* kw = qw + 49*257;        // 49*257
    float* lg = kw + 49*257;        // 49*49
    for (int idx = tid; idx < 49*256; idx += 256){
        int p = idx >> 8, c = idx & 255;
        qw[p*257 + c] = g_qwin[(n*49+p)*256 + c];
        kw[p*257 + c] = g_kwin[(n*49+p)*256 + c];
    }
    __syncthreads();
    for (int idx = tid; idx < 49*49; idx += 256){
        int p = idx / 49, t = idx % 49;
        float acc = 0.f;
        #pragma unroll 8
        for (int c = 0; c < 256; c++) acc += qw[p*257+c] * kw[t*257+c];
        lg[idx] = acc * 0.0625f;
    }
    __syncthreads();
    if (tid < 49){
        float bv[4] = {-1e30f,-1e30f,-1e30f,-1e30f};
        int   bi[4] = {0,0,0,0};
        for (int t = 0; t < 49; t++){
            float v = lg[tid*49 + t];
            if (v > bv[3]){
                int pos = 3;
                while (pos > 0 && v > bv[pos-1]) pos--;
                for (int sft = 3; sft > pos; sft--){ bv[sft]=bv[sft-1]; bi[sft]=bi[sft-1]; }
                bv[pos] = v; bi[pos] = t;
            }
        }
        #pragma unroll
        for (int s = 0; s < 4; s++) g_ridx[(n*49+tid)*4 + s] = bi[s];
    }
}

// ---------------- lepe: 5x5 depthwise conv on v (outputs window-major) ----------------
__global__ void lepe_kernel(const float* __restrict__ w, const float* __restrict__ b){
    int pix = blockIdx.x;
    int c = threadIdx.x;
    int n = pix / 3136, r = pix % 3136;
    int y = r / 56, x = r % 56;
    float acc = b[c];
    #pragma unroll
    for (int ky = 0; ky < 5; ky++){
        int yy = y + ky - 2;
        if ((unsigned)yy >= 56u) continue;
        #pragma unroll
        for (int kx = 0; kx < 5; kx++){
            int xx = x + kx - 2;
            if ((unsigned)xx >= 56u) continue;
            int rw = ((n*49 + (yy>>3)*7 + (xx>>3))<<6) + ((yy&7)<<3) + (xx&7);
            acc += g_qkv[(size_t)rw*768 + 512 + c] * w[(ky*5+kx)*256 + c];
        }
    }
    g_lepe[(size_t)img2win(pix)*256 + c] = acc;
}

// ---------------- attention: one block per (window, head) ----------------
// smem: q[64][36], k[256][36], v[256][36], s[64][257]
__global__ void __launch_bounds__(256) attn_kernel(){
    int np = blockIdx.x;           // 0..391
    int m  = blockIdx.y;           // head 0..7
    int n  = np / 49;
    int tid = threadIdx.x;
    extern __shared__ float sm[];
    float* sq = sm;                 // 64*36  = 2304
    float* sk = sq + 64*36;         // 256*36 = 9216
    float* sv = sk + 256*36;        // 256*36 = 9216
    float* ss = sv + 256*36;        // 64*257 = 16448
    int base = np * 64;

    // load q head-slice
    for (int idx = tid; idx < 2048; idx += 256){
        int r = idx >> 5, d = idx & 31;
        sq[r*36 + d] = g_qkv[(size_t)(base+r)*768 + m*32 + d];
    }
    // gather k,v from 4 selected windows
    #pragma unroll
    for (int s4 = 0; s4 < 4; s4++){
        int wsel = g_ridx[np*4 + s4];
        int sb = (n*49 + wsel) * 64;
        for (int idx = tid; idx < 2048; idx += 256){
            int r = idx >> 5, d = idx & 31;
            int kk = s4*64 + r;
            sk[kk*36 + d] = g_qkv[(size_t)(sb+r)*768 + 256 + m*32 + d];
            sv[kk*36 + d] = g_qkv[(size_t)(sb+r)*768 + 512 + m*32 + d];
        }
    }
    __syncthreads();

    int r  = tid >> 2;    // query row 0..63
    int kq = tid & 3;     // quarter

    // q row into registers
    float4 qreg[8];
    #pragma unroll
    for (int u = 0; u < 8; u++) qreg[u] = *(float4*)&sq[r*36 + u*4];

    // scores (strided k assignment: kk = 4*k2 + kq)
    for (int k2 = 0; k2 < 64; k2++){
        int kk = (k2<<2) + kq;
        float acc = 0.f;
        #pragma unroll
        for (int u = 0; u < 8; u++){
            float4 kv4 = *(float4*)&sk[kk*36 + u*4];
            acc += qreg[u].x*kv4.x + qreg[u].y*kv4.y + qreg[u].z*kv4.z + qreg[u].w*kv4.w;
        }
        ss[r*257 + kk] = acc * 0.0625f;
    }
    // softmax across the quad (no block sync needed: quad lanes in same warp)
    float mx = -1e30f;
    for (int k2 = 0; k2 < 64; k2++) mx = fmaxf(mx, ss[r*257 + (k2<<2) + kq]);
    mx = fmaxf(mx, __shfl_xor_sync(0xffffffffu, mx, 1));
    mx = fmaxf(mx, __shfl_xor_sync(0xffffffffu, mx, 2));
    float sum = 0.f;
    for (int k2 = 0; k2 < 64; k2++){
        int o = r*257 + (k2<<2) + kq;
        float e = expf(ss[o] - mx);
        ss[o] = e; sum += e;
    }
    sum += __shfl_xor_sync(0xffffffffu, sum, 1);
    sum += __shfl_xor_sync(0xffffffffu, sum, 2);
    float invs = 1.f / sum;
    for (int k2 = 0; k2 < 64; k2++) ss[r*257 + (k2<<2) + kq] *= invs;
    __syncthreads();

    // out = aw @ v : thread owns (r, d = kq*8 .. kq*8+7)
    float oa[8] = {0,0,0,0,0,0,0,0};
    for (int p = 0; p < 256; p++){
        float a = ss[r*257 + p];
        float4 v0 = *(float4*)&sv[p*36 + kq*8];
        float4 v1 = *(float4*)&sv[p*36 + kq*8 + 4];
        oa[0] += a*v0.x; oa[1] += a*v0.y; oa[2] += a*v0.z; oa[3] += a*v0.w;
        oa[4] += a*v1.x; oa[5] += a*v1.y; oa[6] += a*v1.z; oa[7] += a*v1.w;
    }
    #pragma unroll
    for (int j = 0; j < 8; j++)
        g_attn[(size_t)(base+r)*256 + m*32 + kq*8 + j] = oa[j];
}

// ---------------- generic fp32 GEMM, 128x128x16 tile, 256 thr, 8x8 microtile --------
// MODE 0: C = A@B + bias                               (qkv)
// MODE 1: C[img] = res[img] + (A+A2)@B + bias, remap   (wo + lepe + residual)
// MODE 2: C = gelu(A@B + bias)                          (mlp1)
// MODE 3: C = res + A@B + bias                          (mlp2 -> out)
template<int MODE>
__global__ void __launch_bounds__(256,2) gemm_kernel(
    const float* __restrict__ A, const float* __restrict__ A2,
    const float* __restrict__ B, const float* __restrict__ bias,
    const float* __restrict__ res, float* __restrict__ Cout,
    int M, int N, int K)
{
    __shared__ float As[16][132];
    __shared__ float Bs[16][132];
    const int tid = threadIdx.x;
    const int m0 = blockIdx.y * 128, n0 = blockIdx.x * 128;
    const int arow = tid >> 1;            // 0..127
    const int acol = (tid & 1) * 8;       // 0 or 8
    const int brow = tid >> 4;            // 0..15
    const int bcol = (tid & 15) * 8;      // 0..120
    const int tm = (tid >> 4) * 8;
    const int tn = (tid & 15) * 8;
    float acc[8][8];
    #pragma unroll
    for (int i = 0; i < 8; i++)
        #pragma unroll
        for (int j = 0; j < 8; j++) acc[i][j] = 0.f;

    const float* Ap  = A + (size_t)(m0+arow)*K + acol;
    const float* A2p = (MODE==1) ? (A2 + (size_t)(m0+arow)*K + acol) : A;
    const float* Bp  = B + (size_t)brow*N + n0 + bcol;

    for (int kt = 0; kt < K; kt += 16){
        float4 a0 = *(const float4*)(Ap + kt);
        float4 a1 = *(const float4*)(Ap + kt + 4);
        if (MODE==1){
            float4 c0 = *(const float4*)(A2p + kt);
            float4 c1 = *(const float4*)(A2p + kt + 4);
            a0.x+=c0.x; a0.y+=c0.y; a0.z+=c0.z; a0.w+=c0.w;
            a1.x+=c1.x; a1.y+=c1.y; a1.z+=c1.z; a1.w+=c1.w;
        }
        float4 b0 = *(const float4*)(Bp + (size_t)kt*N);
        float4 b1 = *(const float4*)(Bp + (size_t)kt*N + 4);
        __syncthreads();
        As[acol+0][arow]=a0.x; As[acol+1][arow]=a0.y; As[acol+2][arow]=a0.z; As[acol+3][arow]=a0.w;
        As[acol+4][arow]=a1.x; As[acol+5][arow]=a1.y; As[acol+6][arow]=a1.z; As[acol+7][arow]=a1.w;
        *(float4*)&Bs[brow][bcol]   = b0;
        *(float4*)&Bs[brow][bcol+4] = b1;
        __syncthreads();
        #pragma unroll
        for (int kk = 0; kk < 16; kk++){
            float4 x0 = *(float4*)&As[kk][tm];
            float4 x1 = *(float4*)&As[kk][tm+4];
            float4 y0 = *(float4*)&Bs[kk][tn];
            float4 y1 = *(float4*)&Bs[kk][tn+4];
            float av[8] = {x0.x,x0.y,x0.z,x0.w,x1.x,x1.y,x1.z,x1.w};
            float bv[8] = {y0.x,y0.y,y0.z,y0.w,y1.x,y1.y,y1.z,y1.w};
            #pragma unroll
            for (int i = 0; i < 8; i++)
                #pragma unroll
                for (int j = 0; j < 8; j++)
                    acc[i][j] += av[i]*bv[j];
        }
    }

    #pragma unroll
    for (int i = 0; i < 8; i++){
        int row = m0 + tm + i;
        int orow = (MODE==1) ? win2img(row) : row;
        #pragma unroll
        for (int j = 0; j < 8; j++){
            int col = n0 + tn + j;
            float v = acc[i][j] + bias[col];
            size_t o = (size_t)orow*N + col;
            if (MODE==0)      Cout[o] = v;
            else if (MODE==1) Cout[o] = res[o] + v;
            else if (MODE==2) Cout[o] = 0.5f*v*(1.f + erff(v*0.70710678118654752f));
            else              Cout[o] = res[o] + v;
        }
    }
}

// ---------------- launch ----------------
extern "C" void kernel_launch(void* const* d_in, const int* in_sizes, int n_in,
                              void* d_out, int out_size)
{
    const float* x      = (const float*)d_in[0];
    const float* ln1_g  = (const float*)d_in[1];
    const float* ln1_b  = (const float*)d_in[2];
    const float* qkv_w  = (const float*)d_in[3];
    const float* qkv_b  = (const float*)d_in[4];
    const float* lepe_w = (const float*)d_in[5];
    const float* lepe_b = (const float*)d_in[6];
    const float* wo_w   = (const float*)d_in[7];
    const float* wo_b   = (const float*)d_in[8];
    const float* ln2_g  = (const float*)d_in[9];
    const float* ln2_b  = (const float*)d_in[10];
    const float* mlp_w1 = (const float*)d_in[11];
    const float* mlp_b1 = (const float*)d_in[12];
    const float* mlp_w2 = (const float*)d_in[13];
    const float* mlp_b2 = (const float*)d_in[14];
    float* out = (float*)d_out;

    float *p_xn,*p_qkv,*p_lepe,*p_attn,*p_x2,*p_ln2,*p_hid;
    cudaGetSymbolAddress((void**)&p_xn,   g_xn);
    cudaGetSymbolAddress((void**)&p_qkv,  g_qkv);
    cudaGetSymbolAddress((void**)&p_lepe, g_lepe);
    cudaGetSymbolAddress((void**)&p_attn, g_attn);
    cudaGetSymbolAddress((void**)&p_x2,   g_x2);
    cudaGetSymbolAddress((void**)&p_ln2,  g_ln2);
    cudaGetSymbolAddress((void**)&p_hid,  g_hid);

    // 1. LN1 -> window layout
    ln_kernel<true><<<PIX/8, 256>>>(x, ln1_g, ln1_b, p_xn);
    // 2. qkv GEMM [25088,256]x[256,768]
    gemm_kernel<0><<<dim3(768/128, PIX/128), 256>>>(p_xn, nullptr, qkv_w, qkv_b, nullptr, p_qkv, PIX, 768, 256);
    // 3. window means
    win_mean_kernel<<<NWIN, 256>>>();
    // 4. logits + top-4
    {
        int lsm = (2*49*257 + 49*49) * 4;
        cudaFuncSetAttribute(logit_topk_kernel, cudaFuncAttributeMaxDynamicSharedMemorySize, lsm);
        logit_topk_kernel<<<8, 256, lsm>>>();
    }
    // 5. lepe depthwise conv
    lepe_kernel<<<PIX, 256>>>(lepe_w, lepe_b);
    // 6. attention
    {
        int asmB = (64*36 + 2*256*36 + 64*257) * 4;
        cudaFuncSetAttribute(attn_kernel, cudaFuncAttributeMaxDynamicSharedMemorySize, asmB);
        attn_kernel<<<dim3(NWIN, 8), 256, asmB>>>();
    }
    // 7. wo GEMM: x2[img] = x + (attn+lepe)@wo + b
    gemm_kernel<1><<<dim3(256/128, PIX/128), 256>>>(p_attn, p_lepe, wo_w, wo_b, x, p_x2, PIX, 256, 256);
    // 8. LN2
    ln_kernel<false><<<PIX/8, 256>>>(p_x2, ln2_g, ln2_b, p_ln2);
    // 9. mlp1 + gelu
    gemm_kernel<2><<<dim3(1024/128, PIX/128), 256>>>(p_ln2, nullptr, mlp_w1, mlp_b1, nullptr, p_hid, PIX, 1024, 256);
    // 10. mlp2 + residual -> out
    gemm_kernel<3><<<dim3(256/128, PIX/128), 256>>>(p_hid, nullptr, mlp_w2, mlp_b2, p_x2, out, PIX, 256, 1024);
}

// round 9
// speedup vs baseline: 1.4169x; 1.4169x over previous
#include <cuda_runtime.h>
#include <cuda_bf16.h>
#include <math.h>
#include <stdint.h>

#define PIX 25088           // 8*56*56
#define NWIN 392            // 8*49

// ---------------- device scratch ----------------
__device__ __align__(128) float g_qkv [PIX*768];          // qkv fp32, window-major rows
__device__ __align__(128) __nv_bfloat16 g_ahi[PIX*256];   // generic A operand hi (reused)
__device__ __align__(128) __nv_bfloat16 g_alo[PIX*256];   // generic A operand lo
__device__ __align__(128) float g_xbar[NWIN*256];
__device__ __align__(128) float g_qwin[NWIN*256];
__device__ __align__(128) float g_kwin[NWIN*256];
__device__ __align__(128) int   g_ridx[NWIN*4];
__device__ __align__(128) float g_lepe[PIX*256];          // window-major
__device__ __align__(128) float g_attn[PIX*256];          // window-major
__device__ __align__(128) float g_x2  [PIX*256];          // image-major residual stream
__device__ __align__(128) __nv_bfloat16 g_hhi[PIX*1024];  // mlp hidden hi
__device__ __align__(128) __nv_bfloat16 g_hlo[PIX*1024];  // mlp hidden lo
__device__ __align__(128) __nv_bfloat16 g_wth[786432];    // transposed weights hi [N][K]
__device__ __align__(128) __nv_bfloat16 g_wtl[786432];    // transposed weights lo
#define OFF_QKV 0
#define OFF_WO  196608
#define OFF_M1  262144
#define OFF_M2  524288

// ---------------- layout maps ----------------
__device__ __forceinline__ int img2win(int pix){
    int n = pix / 3136, r = pix % 3136;
    int y = r / 56, x = r % 56;
    return (n*49 + (y>>3)*7 + (x>>3))*64 + ((y&7)<<3) + (x&7);
}
__device__ __forceinline__ int win2img(int rw){
    int n = rw / 3136, r = rw % 3136;
    int p = r >> 6, q = r & 63;
    int y = ((p/7)<<3) + (q>>3), x = ((p%7)<<3) + (q&7);
    return n*3136 + y*56 + x;
}

// ---------------- helpers ----------------
__device__ __forceinline__ uint32_t smem_u32(const void* p){
    uint32_t a;
    asm("{ .reg .u64 t; cvta.to.shared.u64 t, %1; cvt.u32.u64 %0, t; }" : "=r"(a) : "l"(p));
    return a;
}
__device__ __forceinline__ void ldmA(uint32_t* a, uint32_t addr){
    asm volatile("ldmatrix.sync.aligned.m8n8.x4.shared.b16 {%0,%1,%2,%3}, [%4];"
        : "=r"(a[0]),"=r"(a[1]),"=r"(a[2]),"=r"(a[3]) : "r"(addr));
}
__device__ __forceinline__ void ldmB(uint32_t* b, uint32_t addr){
    asm volatile("ldmatrix.sync.aligned.m8n8.x2.shared.b16 {%0,%1}, [%2];"
        : "=r"(b[0]),"=r"(b[1]) : "r"(addr));
}
__device__ __forceinline__ void mma16816(float* c, const uint32_t* a, const uint32_t* b){
    asm volatile("mma.sync.aligned.m16n8k16.row.col.f32.bf16.bf16.f32 "
        "{%0,%1,%2,%3}, {%4,%5,%6,%7}, {%8,%9}, {%0,%1,%2,%3};"
        : "+f"(c[0]),"+f"(c[1]),"+f"(c[2]),"+f"(c[3])
        : "r"(a[0]),"r"(a[1]),"r"(a[2]),"r"(a[3]), "r"(b[0]),"r"(b[1]));
}
__device__ __forceinline__ uint32_t packbf2(__nv_bfloat16 a, __nv_bfloat16 b){
    return (uint32_t)__bfloat16_as_ushort(a) | ((uint32_t)__bfloat16_as_ushort(b) << 16);
}
__device__ __forceinline__ void split8(const float* v, uint4& uh, uint4& ul){
    __nv_bfloat16 h[8], l[8];
    #pragma unroll
    for (int j = 0; j < 8; j++){
        h[j] = __float2bfloat16(v[j]);
        l[j] = __float2bfloat16(v[j] - __bfloat162float(h[j]));
    }
    uh = make_uint4(packbf2(h[0],h[1]), packbf2(h[2],h[3]), packbf2(h[4],h[5]), packbf2(h[6],h[7]));
    ul = make_uint4(packbf2(l[0],l[1]), packbf2(l[2],l[3]), packbf2(l[4],l[5]), packbf2(l[6],l[7]));
}

// ---------------- LayerNorm -> bf16 hi/lo ----------------
template<bool REMAP>
__global__ void ln_kernel(const float* __restrict__ in, const float* __restrict__ g,
                          const float* __restrict__ b,
                          __nv_bfloat16* __restrict__ oh, __nv_bfloat16* __restrict__ ol){
    int warp = threadIdx.x >> 5, lane = threadIdx.x & 31;
    int pix = blockIdx.x * 8 + warp;
    const float* row = in + (size_t)pix * 256;
    int c0 = lane * 8;
    float4 v0 = *(const float4*)(row + c0);
    float4 v1 = *(const float4*)(row + c0 + 4);
    float vals[8] = {v0.x,v0.y,v0.z,v0.w,v1.x,v1.y,v1.z,v1.w};
    float s = 0.f, ss = 0.f;
    #pragma unroll
    for (int u = 0; u < 8; u++){ s += vals[u]; ss += vals[u]*vals[u]; }
    #pragma unroll
    for (int o = 16; o; o >>= 1){
        s  += __shfl_xor_sync(0xffffffffu, s,  o);
        ss += __shfl_xor_sync(0xffffffffu, ss, o);
    }
    float mu  = s * (1.f/256.f);
    float var = ss * (1.f/256.f) - mu*mu;
    float inv = rsqrtf(var + 1e-6f);
    int orow = REMAP ? img2win(pix) : pix;
    float ov[8];
    #pragma unroll
    for (int u = 0; u < 8; u++) ov[u] = (vals[u]-mu)*inv*g[c0+u] + b[c0+u];
    uint4 uh, ul;
    split8(ov, uh, ul);
    *(uint4*)&oh[(size_t)orow*256 + c0] = uh;
    *(uint4*)&ol[(size_t)orow*256 + c0] = ul;
}

// ---------------- weight transpose + split: w[K][N] -> wT hi/lo [N][K] ----------------
__global__ void wtrans_kernel(const float* __restrict__ w, __nv_bfloat16* __restrict__ th,
                              __nv_bfloat16* __restrict__ tl, int K, int N){
    __shared__ float t[32][33];
    int n0 = blockIdx.x*32, k0 = blockIdx.y*32;
    int tx = threadIdx.x, ty = threadIdx.y;
    for (int r = ty; r < 32; r += 8) t[r][tx] = w[(size_t)(k0+r)*N + n0+tx];
    __syncthreads();
    for (int r = ty; r < 32; r += 8){
        float v = t[tx][r];
        __nv_bfloat16 h = __float2bfloat16(v);
        th[(size_t)(n0+r)*K + k0+tx] = h;
        tl[(size_t)(n0+r)*K + k0+tx] = __float2bfloat16(v - __bfloat162float(h));
    }
}

// ---------------- window mean of x (hi+lo, exact routing path) ----------------
__global__ void winmeanx_kernel(){
    int np = blockIdx.x, c = threadIdx.x;
    float s = 0.f;
    #pragma unroll 4
    for (int r = 0; r < 64; r++){
        size_t i = (size_t)(np*64+r)*256 + c;
        s += __bfloat162float(g_ahi[i]) + __bfloat162float(g_alo[i]);
    }
    g_xbar[np*256 + c] = s * (1.f/64.f);
}

// ---------------- q_win/k_win = xbar @ Wq/Wk + b (fp32 exact) ----------------
__global__ void winproj_kernel(const float* __restrict__ qkv_w, const float* __restrict__ qkv_b){
    __shared__ float sx[256];
    int np = blockIdx.x, c = threadIdx.x;
    sx[c] = g_xbar[np*256 + c];
    __syncthreads();
    float qa = qkv_b[c], ka = qkv_b[256 + c];
    #pragma unroll 8
    for (int d = 0; d < 256; d++){
        float xv = sx[d];
        qa += xv * qkv_w[d*768 + c];
        ka += xv * qkv_w[d*768 + 256 + c];
    }
    g_qwin[np*256 + c] = qa;
    g_kwin[np*256 + c] = ka;
}

// ---------------- logits + top-4 (one block per window) ----------------
// NOTE: shuffles are executed by ALL threads (convergent); only stores are guarded.
__global__ void logit_topk_kernel(){
    __shared__ float sq[256];
    __shared__ float sl[64];
    int np = blockIdx.x, n = np / 49;
    int tid = threadIdx.x;
    sq[tid] = g_qwin[np*256 + tid];
    if (tid < 64) sl[tid] = -1e30f;
    __syncthreads();
    int t = tid >> 2, part = tid & 3;
    int tc = (t < 49) ? t : 48;                       // clamp: keeps reads in-bounds
    const float* kr = &g_kwin[(size_t)(n*49 + tc)*256 + part*64];
    float acc = 0.f;
    #pragma unroll 8
    for (int c = 0; c < 64; c++) acc += sq[part*64 + c] * kr[c];
    acc += __shfl_xor_sync(0xffffffffu, acc, 1);      // convergent: all 32 lanes participate
    acc += __shfl_xor_sync(0xffffffffu, acc, 2);
    if (part == 0 && t < 49) sl[t] = acc * 0.0625f;
    __syncthreads();
    if (tid == 0){
        float bv[4] = {-1e30f,-1e30f,-1e30f,-1e30f};
        int   bi[4] = {0,0,0,0};
        for (int k = 0; k < 49; k++){
            float v = sl[k];
            if (v > bv[3]){
                int pos = 3;
                while (pos > 0 && v > bv[pos-1]) pos--;
                for (int sft = 3; sft > pos; sft--){ bv[sft]=bv[sft-1]; bi[sft]=bi[sft-1]; }
                bv[pos] = v; bi[pos] = k;
            }
        }
        #pragma unroll
        for (int s = 0; s < 4; s++) g_ridx[np*4 + s] = bi[s];
    }
}

// ---------------- lepe: 5x5 depthwise conv on v ----------------
__global__ void lepe_kernel(const float* __restrict__ w, const float* __restrict__ b){
    int pix = blockIdx.x;
    int c = threadIdx.x;
    int n = pix / 3136, r = pix % 3136;
    int y = r / 56, x = r % 56;
    float acc = b[c];
    #pragma unroll
    for (int ky = 0; ky < 5; ky++){
        int yy = y + ky - 2;
        if ((unsigned)yy >= 56u) continue;
        #pragma unroll
        for (int kx = 0; kx < 5; kx++){
            int xx = x + kx - 2;
            if ((unsigned)xx >= 56u) continue;
            int rw = ((n*49 + (yy>>3)*7 + (xx>>3))<<6) + ((yy&7)<<3) + (xx&7);
            acc += g_qkv[(size_t)rw*768 + 512 + c] * w[(ky*5+kx)*256 + c];
        }
    }
    g_lepe[(size_t)img2win(pix)*256 + c] = acc;
}

// ---------------- attention: one block per (window, head) ----------------
__global__ void __launch_bounds__(256) attn_kernel(){
    int np = blockIdx.x;
    int m  = blockIdx.y;
    int n  = np / 49;
    int tid = threadIdx.x;
    extern __shared__ float sm[];
    float* sq = sm;                 // 64*36
    float* sk = sq + 64*36;         // 256*36
    float* sv = sk + 256*36;        // 256*36
    float* ss = sv + 256*36;        // 64*257
    int base = np * 64;

    for (int idx = tid; idx < 2048; idx += 256){
        int r = idx >> 5, d = idx & 31;
        sq[r*36 + d] = g_qkv[(size_t)(base+r)*768 + m*32 + d];
    }
    #pragma unroll
    for (int s4 = 0; s4 < 4; s4++){
        int wsel = g_ridx[np*4 + s4];
        int sb = (n*49 + wsel) * 64;
        for (int idx = tid; idx < 2048; idx += 256){
            int r = idx >> 5, d = idx & 31;
            int kk = s4*64 + r;
            sk[kk*36 + d] = g_qkv[(size_t)(sb+r)*768 + 256 + m*32 + d];
            sv[kk*36 + d] = g_qkv[(size_t)(sb+r)*768 + 512 + m*32 + d];
        }
    }
    __syncthreads();

    int r  = tid >> 2;
    int kq = tid & 3;
    float4 qreg[8];
    #pragma unroll
    for (int u = 0; u < 8; u++) qreg[u] = *(float4*)&sq[r*36 + u*4];

    for (int k2 = 0; k2 < 64; k2++){
        int kk = (k2<<2) + kq;
        float acc = 0.f;
        #pragma unroll
        for (int u = 0; u < 8; u++){
            float4 kv4 = *(float4*)&sk[kk*36 + u*4];
            acc += qreg[u].x*kv4.x + qreg[u].y*kv4.y + qreg[u].z*kv4.z + qreg[u].w*kv4.w;
        }
        ss[r*257 + kk] = acc * 0.0625f;
    }
    float mx = -1e30f;
    for (int k2 = 0; k2 < 64; k2++) mx = fmaxf(mx, ss[r*257 + (k2<<2) + kq]);
    mx = fmaxf(mx, __shfl_xor_sync(0xffffffffu, mx, 1));
    mx = fmaxf(mx, __shfl_xor_sync(0xffffffffu, mx, 2));
    float sum = 0.f;
    for (int k2 = 0; k2 < 64; k2++){
        int o = r*257 + (k2<<2) + kq;
        float e = expf(ss[o] - mx);
        ss[o] = e; sum += e;
    }
    sum += __shfl_xor_sync(0xffffffffu, sum, 1);
    sum += __shfl_xor_sync(0xffffffffu, sum, 2);
    float invs = 1.f / sum;
    for (int k2 = 0; k2 < 64; k2++) ss[r*257 + (k2<<2) + kq] *= invs;
    __syncthreads();

    float oa[8] = {0,0,0,0,0,0,0,0};
    for (int p = 0; p < 256; p++){
        float a = ss[r*257 + p];
        float4 v0 = *(float4*)&sv[p*36 + kq*8];
        float4 v1 = *(float4*)&sv[p*36 + kq*8 + 4];
        oa[0] += a*v0.x; oa[1] += a*v0.y; oa[2] += a*v0.z; oa[3] += a*v0.w;
        oa[4] += a*v1.x; oa[5] += a*v1.y; oa[6] += a*v1.z; oa[7] += a*v1.w;
    }
    #pragma unroll
    for (int j = 0; j < 8; j++)
        g_attn[(size_t)(base+r)*256 + m*32 + kq*8 + j] = oa[j];
}

// ---------------- add attn+lepe, split to bf16 hi/lo ----------------
__global__ void addcvt_kernel(){
    size_t i0 = ((size_t)blockIdx.x*256 + threadIdx.x)*8;
    float4 a0 = *(float4*)&g_attn[i0], a1 = *(float4*)&g_attn[i0+4];
    float4 b0 = *(float4*)&g_lepe[i0], b1 = *(float4*)&g_lepe[i0+4];
    float v[8] = {a0.x+b0.x, a0.y+b0.y, a0.z+b0.z, a0.w+b0.w,
                  a1.x+b1.x, a1.y+b1.y, a1.z+b1.z, a1.w+b1.w};
    uint4 uh, ul;
    split8(v, uh, ul);
    *(uint4*)&g_ahi[i0] = uh;
    *(uint4*)&g_alo[i0] = ul;
}

// ---------------- mma.sync split-bf16 GEMM: 128x128 tile, BK=32 ----
// Single smem buffer + register prefetch (plain LDG/STS, no cp.async).
// A[M][K] bf16 (hi/lo), B[N][K] bf16 (hi/lo). 3 passes: hiA*hiB, loA*hiB, hiA*loB.
// MODE 0: outf = A@B + bias                       (qkv)
// MODE 1: outf[win2img] = res + A@B + bias        (wo + residual, layout remap)
// MODE 2: outh/outl = split(gelu(A@B + bias))      (mlp1)
// MODE 3: outf = res + A@B + bias                  (mlp2 -> final out)
#define LDH 40   // smem row stride in halves (80B: conflict-free ldmatrix)
template<int MODE>
__global__ void __launch_bounds__(256) mgemm_kernel(
    const __nv_bfloat16* __restrict__ Ahi, const __nv_bfloat16* __restrict__ Alo,
    const __nv_bfloat16* __restrict__ Bhi, const __nv_bfloat16* __restrict__ Blo,
    const float* __restrict__ bias, const float* __restrict__ res,
    float* __restrict__ outf, __nv_bfloat16* __restrict__ outh, __nv_bfloat16* __restrict__ outl,
    int N, int K)
{
    __shared__ __align__(16) __nv_bfloat16 sA[128*LDH];
    __shared__ __align__(16) __nv_bfloat16 sB[128*LDH];
    const int tid = threadIdx.x, w = tid >> 5, lane = tid & 31;
    const int m0 = blockIdx.y * 128, n0 = blockIdx.x * 128;
    const int wm = (w >> 2) * 64, wn = (w & 3) * 32;
    const int kch = K / 32;
    const int NCH = 3 * kch;

    const uint32_t saA = smem_u32(sA), saB = smem_u32(sB);

    const int rA = tid >> 2;
    const int sg = (tid & 3) * 8;

    float acc[4][4][4];
    #pragma unroll
    for (int i = 0; i < 4; i++)
        #pragma unroll
        for (int j = 0; j < 4; j++)
            #pragma unroll
            for (int q = 0; q < 4; q++) acc[i][j][q] = 0.f;

    uint4 pa0 = *(const uint4*)(Ahi + (size_t)(m0+rA)*K + sg);
    uint4 pa1 = *(const uint4*)(Ahi + (size_t)(m0+64+rA)*K + sg);
    uint4 pb0 = *(const uint4*)(Bhi + (size_t)(n0+rA)*K + sg);
    uint4 pb1 = *(const uint4*)(Bhi + (size_t)(n0+64+rA)*K + sg);

    for (int c = 0; c < NCH; c++){
        *(uint4*)&sA[rA*LDH + sg]      = pa0;
        *(uint4*)&sA[(64+rA)*LDH + sg] = pa1;
        *(uint4*)&sB[rA*LDH + sg]      = pb0;
        *(uint4*)&sB[(64+rA)*LDH + sg] = pb1;
        __syncthreads();

        if (c + 1 < NCH){
            int cn = c + 1;
            int p = cn / kch, ko = (cn - p*kch) * 32;
            const __nv_bfloat16* Ag = (p == 1) ? Alo : Ahi;
            const __nv_bfloat16* Bg = (p == 2) ? Blo : Bhi;
            pa0 = *(const uint4*)(Ag + (size_t)(m0+rA)*K + ko + sg);
            pa1 = *(const uint4*)(Ag + (size_t)(m0+64+rA)*K + ko + sg);
            pb0 = *(const uint4*)(Bg + (size_t)(n0+rA)*K + ko + sg);
            pb1 = *(const uint4*)(Bg + (size_t)(n0+64+rA)*K + ko + sg);
        }

        #pragma unroll
        for (int ks = 0; ks < 2; ks++){
            const int kk = ks * 16;
            uint32_t afr[4][4], bfr[4][2];
            uint32_t aaddr = saA + (uint32_t)((wm + (lane & 15))*LDH + kk + ((lane >> 4) & 1)*8) * 2;
            #pragma unroll
            for (int mt = 0; mt < 4; mt++)
                ldmA(afr[mt], aaddr + mt*16*LDH*2);
            uint32_t baddr = saB + (uint32_t)((wn + (lane & 7))*LDH + kk + ((lane >> 3) & 1)*8) * 2;
            #pragma unroll
            for (int nt = 0; nt < 4; nt++)
                ldmB(bfr[nt], baddr + nt*8*LDH*2);
            #pragma unroll
            for (int mt = 0; mt < 4; mt++)
                #pragma unroll
                for (int nt = 0; nt < 4; nt++)
                    mma16816(acc[mt][nt], afr[mt], bfr[nt]);
        }
        __syncthreads();
    }

    // epilogue
    #pragma unroll
    for (int mt = 0; mt < 4; mt++){
        int r0 = m0 + wm + mt*16 + (lane >> 2);
        int r1 = r0 + 8;
        int o0 = (MODE == 1) ? win2img(r0) : r0;
        int o1 = (MODE == 1) ? win2img(r1) : r1;
        #pragma unroll
        for (int nt = 0; nt < 4; nt++){
            int col = n0 + wn + nt*8 + (lane & 3)*2;
            float b0 = bias[col], b1 = bias[col+1];
            float v00 = acc[mt][nt][0] + b0, v01 = acc[mt][nt][1] + b1;
            float v10 = acc[mt][nt][2] + b0, v11 = acc[mt][nt][3] + b1;
            if (MODE == 2){
                v00 = 0.5f*v00*(1.f + erff(v00*0.70710678118654752f));
                v01 = 0.5f*v01*(1.f + erff(v01*0.70710678118654752f));
                v10 = 0.5f*v10*(1.f + erff(v10*0.70710678118654752f));
                v11 = 0.5f*v11*(1.f + erff(v11*0.70710678118654752f));
                __nv_bfloat16 h00 = __float2bfloat16(v00), h01 = __float2bfloat16(v01);
                __nv_bfloat16 h10 = __float2bfloat16(v10), h11 = __float2bfloat16(v11);
                *(uint32_t*)&outh[(size_t)o0*N + col] = packbf2(h00, h01);
                *(uint32_t*)&outh[(size_t)o1*N + col] = packbf2(h10, h11);
                *(uint32_t*)&outl[(size_t)o0*N + col] = packbf2(
                    __float2bfloat16(v00 - __bfloat162float(h00)),
                    __float2bfloat16(v01 - __bfloat162float(h01)));
                *(uint32_t*)&outl[(size_t)o1*N + col] = packbf2(
                    __float2bfloat16(v10 - __bfloat162float(h10)),
                    __float2bfloat16(v11 - __bfloat162float(h11)));
            } else {
                if (MODE == 1 || MODE == 3){
                    v00 += res[(size_t)o0*N + col];   v01 += res[(size_t)o0*N + col + 1];
                    v10 += res[(size_t)o1*N + col];   v11 += res[(size_t)o1*N + col + 1];
                }
                *(float2*)&outf[(size_t)o0*N + col] = make_float2(v00, v01);
                *(float2*)&outf[(size_t)o1*N + col] = make_float2(v10, v11);
            }
        }
    }
}

// ---------------- launch ----------------
extern "C" void kernel_launch(void* const* d_in, const int* in_sizes, int n_in,
                              void* d_out, int out_size)
{
    const float* x      = (const float*)d_in[0];
    const float* ln1_g  = (const float*)d_in[1];
    const float* ln1_b  = (const float*)d_in[2];
    const float* qkv_w  = (const float*)d_in[3];
    const float* qkv_b  = (const float*)d_in[4];
    const float* lepe_w = (const float*)d_in[5];
    const float* lepe_b = (const float*)d_in[6];
    const float* wo_w   = (const float*)d_in[7];
    const float* wo_b   = (const float*)d_in[8];
    const float* ln2_g  = (const float*)d_in[9];
    const float* ln2_b  = (const float*)d_in[10];
    const float* mlp_w1 = (const float*)d_in[11];
    const float* mlp_b1 = (const float*)d_in[12];
    const float* mlp_w2 = (const float*)d_in[13];
    const float* mlp_b2 = (const float*)d_in[14];
    float* out = (float*)d_out;

    float *p_qkv, *p_x2;
    __nv_bfloat16 *p_ahi, *p_alo, *p_hhi, *p_hlo, *p_wth, *p_wtl;
    cudaGetSymbolAddress((void**)&p_qkv, g_qkv);
    cudaGetSymbolAddress((void**)&p_x2,  g_x2);
    cudaGetSymbolAddress((void**)&p_ahi, g_ahi);
    cudaGetSymbolAddress((void**)&p_alo, g_alo);
    cudaGetSymbolAddress((void**)&p_hhi, g_hhi);
    cudaGetSymbolAddress((void**)&p_hlo, g_hlo);
    cudaGetSymbolAddress((void**)&p_wth, g_wth);
    cudaGetSymbolAddress((void**)&p_wtl, g_wtl);

    // 0. transpose + split all weights
    wtrans_kernel<<<dim3(768/32, 256/32),  dim3(32,8)>>>(qkv_w,  p_wth+OFF_QKV, p_wtl+OFF_QKV, 256, 768);
    wtrans_kernel<<<dim3(256/32, 256/32),  dim3(32,8)>>>(wo_w,   p_wth+OFF_WO,  p_wtl+OFF_WO,  256, 256);
    wtrans_kernel<<<dim3(1024/32, 256/32), dim3(32,8)>>>(mlp_w1, p_wth+OFF_M1,  p_wtl+OFF_M1,  256, 1024);
    wtrans_kernel<<<dim3(256/32, 1024/32), dim3(32,8)>>>(mlp_w2, p_wth+OFF_M2,  p_wtl+OFF_M2,  1024, 256);
    // 1. LN1 -> window layout, bf16 split
    ln_kernel<true><<<PIX/8, 256>>>(x, ln1_g, ln1_b, p_ahi, p_alo);
    // 2. exact routing path: window means + q/k projection + top-4
    winmeanx_kernel<<<NWIN, 256>>>();
    winproj_kernel<<<NWIN, 256>>>(qkv_w, qkv_b);
    logit_topk_kernel<<<NWIN, 256>>>();
    // 3. qkv GEMM
    mgemm_kernel<0><<<dim3(6, 196), 256>>>(p_ahi, p_alo, p_wth+OFF_QKV, p_wtl+OFF_QKV,
                                           qkv_b, nullptr, p_qkv, nullptr, nullptr, 768, 256);
    // 4. lepe + attention
    lepe_kernel<<<PIX, 256>>>(lepe_w, lepe_b);
    {
        int asmB = (64*36 + 2*256*36 + 64*257) * 4;
        cudaFuncSetAttribute(attn_kernel, cudaFuncAttributeMaxDynamicSharedMemorySize, asmB);
        attn_kernel<<<dim3(NWIN, 8), 256, asmB>>>();
    }
    // 5. (attn + lepe) -> bf16 split
    addcvt_kernel<<<PIX*256/2048, 256>>>();
    // 6. wo GEMM + residual + layout remap
    mgemm_kernel<1><<<dim3(2, 196), 256>>>(p_ahi, p_alo, p_wth+OFF_WO, p_wtl+OFF_WO,
                                           wo_b, x, p_x2, nullptr, nullptr, 256, 256);
    // 7. LN2 -> bf16 split
    ln_kernel<false><<<PIX/8, 256>>>(p_x2, ln2_g, ln2_b, p_ahi, p_alo);
    // 8. mlp1 + gelu -> bf16 split
    mgemm_kernel<2><<<dim3(8, 196), 256>>>(p_ahi, p_alo, p_wth+OFF_M1, p_wtl+OFF_M1,
                                           mlp_b1, nullptr, nullptr, p_hhi, p_hlo, 1024, 256);
    // 9. mlp2 + residual -> out
    mgemm_kernel<3><<<dim3(2, 196), 256>>>(p_hhi, p_hlo, p_wth+OFF_M2, p_wtl+OFF_M2,
                                           mlp_b2, p_x2, out, nullptr, nullptr, 256, 1024);
}

// round 10
// speedup vs baseline: 1.6868x; 1.1904x over previous
#include <cuda_runtime.h>
#include <cuda_bf16.h>
#include <math.h>
#include <stdint.h>

#define PIX 25088           // 8*56*56
#define NWIN 392            // 8*49

// ---------------- device scratch ----------------
__device__ __align__(128) float g_qkv [PIX*768];          // qkv fp32, window-major rows
__device__ __align__(128) __nv_bfloat16 g_ahi[PIX*256];   // generic A operand hi (reused)
__device__ __align__(128) __nv_bfloat16 g_alo[PIX*256];   // generic A operand lo
__device__ __align__(128) float g_xbar[NWIN*256];
__device__ __align__(128) float g_qwin[NWIN*256];
__device__ __align__(128) float g_kwin[NWIN*256];
__device__ __align__(128) int   g_ridx[NWIN*4];
__device__ __align__(128) float g_lepe[PIX*256];          // window-major
__device__ __align__(128) float g_attn[PIX*256];          // window-major
__device__ __align__(128) float g_x2  [PIX*256];          // image-major residual stream
__device__ __align__(128) __nv_bfloat16 g_hhi[PIX*1024];  // mlp hidden hi
__device__ __align__(128) __nv_bfloat16 g_hlo[PIX*1024];  // mlp hidden lo
__device__ __align__(128) __nv_bfloat16 g_wth[786432];    // transposed weights hi [N][K]
__device__ __align__(128) __nv_bfloat16 g_wtl[786432];    // transposed weights lo
#define OFF_QKV 0
#define OFF_WO  196608
#define OFF_M1  262144
#define OFF_M2  524288

// ---------------- layout maps ----------------
__device__ __forceinline__ int img2win(int pix){
    int n = pix / 3136, r = pix % 3136;
    int y = r / 56, x = r % 56;
    return (n*49 + (y>>3)*7 + (x>>3))*64 + ((y&7)<<3) + (x&7);
}
__device__ __forceinline__ int win2img(int rw){
    int n = rw / 3136, r = rw % 3136;
    int p = r >> 6, q = r & 63;
    int y = ((p/7)<<3) + (q>>3), x = ((p%7)<<3) + (q&7);
    return n*3136 + y*56 + x;
}

// ---------------- helpers ----------------
__device__ __forceinline__ uint32_t smem_u32(const void* p){
    uint32_t a;
    asm("{ .reg .u64 t; cvta.to.shared.u64 t, %1; cvt.u32.u64 %0, t; }" : "=r"(a) : "l"(p));
    return a;
}
__device__ __forceinline__ void cp16(uint32_t saddr, const void* gaddr){
    asm volatile("cp.async.cg.shared.global [%0], [%1], 16;" :: "r"(saddr), "l"(gaddr));
}
__device__ __forceinline__ void ldmA(uint32_t* a, uint32_t addr){
    asm volatile("ldmatrix.sync.aligned.m8n8.x4.shared.b16 {%0,%1,%2,%3}, [%4];"
        : "=r"(a[0]),"=r"(a[1]),"=r"(a[2]),"=r"(a[3]) : "r"(addr));
}
__device__ __forceinline__ void ldmB(uint32_t* b, uint32_t addr){
    asm volatile("ldmatrix.sync.aligned.m8n8.x2.shared.b16 {%0,%1}, [%2];"
        : "=r"(b[0]),"=r"(b[1]) : "r"(addr));
}
__device__ __forceinline__ void mma16816(float* c, const uint32_t* a, const uint32_t* b){
    asm volatile("mma.sync.aligned.m16n8k16.row.col.f32.bf16.bf16.f32 "
        "{%0,%1,%2,%3}, {%4,%5,%6,%7}, {%8,%9}, {%0,%1,%2,%3};"
        : "+f"(c[0]),"+f"(c[1]),"+f"(c[2]),"+f"(c[3])
        : "r"(a[0]),"r"(a[1]),"r"(a[2]),"r"(a[3]), "r"(b[0]),"r"(b[1]));
}
__device__ __forceinline__ uint32_t packbf2(__nv_bfloat16 a, __nv_bfloat16 b){
    return (uint32_t)__bfloat16_as_ushort(a) | ((uint32_t)__bfloat16_as_ushort(b) << 16);
}
__device__ __forceinline__ void split8(const float* v, uint4& uh, uint4& ul){
    __nv_bfloat16 h[8], l[8];
    #pragma unroll
    for (int j = 0; j < 8; j++){
        h[j] = __float2bfloat16(v[j]);
        l[j] = __float2bfloat16(v[j] - __bfloat162float(h[j]));
    }
    uh = make_uint4(packbf2(h[0],h[1]), packbf2(h[2],h[3]), packbf2(h[4],h[5]), packbf2(h[6],h[7]));
    ul = make_uint4(packbf2(l[0],l[1]), packbf2(l[2],l[3]), packbf2(l[4],l[5]), packbf2(l[6],l[7]));
}

// ---------------- LayerNorm -> bf16 hi/lo ----------------
template<bool REMAP>
__global__ void ln_kernel(const float* __restrict__ in, const float* __restrict__ g,
                          const float* __restrict__ b,
                          __nv_bfloat16* __restrict__ oh, __nv_bfloat16* __restrict__ ol){
    int warp = threadIdx.x >> 5, lane = threadIdx.x & 31;
    int pix = blockIdx.x * 8 + warp;
    const float* row = in + (size_t)pix * 256;
    int c0 = lane * 8;
    float4 v0 = *(const float4*)(row + c0);
    float4 v1 = *(const float4*)(row + c0 + 4);
    float vals[8] = {v0.x,v0.y,v0.z,v0.w,v1.x,v1.y,v1.z,v1.w};
    float s = 0.f, ss = 0.f;
    #pragma unroll
    for (int u = 0; u < 8; u++){ s += vals[u]; ss += vals[u]*vals[u]; }
    #pragma unroll
    for (int o = 16; o; o >>= 1){
        s  += __shfl_xor_sync(0xffffffffu, s,  o);
        ss += __shfl_xor_sync(0xffffffffu, ss, o);
    }
    float mu  = s * (1.f/256.f);
    float var = ss * (1.f/256.f) - mu*mu;
    float inv = rsqrtf(var + 1e-6f);
    int orow = REMAP ? img2win(pix) : pix;
    float ov[8];
    #pragma unroll
    for (int u = 0; u < 8; u++) ov[u] = (vals[u]-mu)*inv*g[c0+u] + b[c0+u];
    uint4 uh, ul;
    split8(ov, uh, ul);
    *(uint4*)&oh[(size_t)orow*256 + c0] = uh;
    *(uint4*)&ol[(size_t)orow*256 + c0] = ul;
}

// ---------------- weight transpose + split: w[K][N] -> wT hi/lo [N][K] ----------------
__global__ void wtrans_kernel(const float* __restrict__ w, __nv_bfloat16* __restrict__ th,
                              __nv_bfloat16* __restrict__ tl, int K, int N){
    __shared__ float t[32][33];
    int n0 = blockIdx.x*32, k0 = blockIdx.y*32;
    int tx = threadIdx.x, ty = threadIdx.y;
    for (int r = ty; r < 32; r += 8) t[r][tx] = w[(size_t)(k0+r)*N + n0+tx];
    __syncthreads();
    for (int r = ty; r < 32; r += 8){
        float v = t[tx][r];
        __nv_bfloat16 h = __float2bfloat16(v);
        th[(size_t)(n0+r)*K + k0+tx] = h;
        tl[(size_t)(n0+r)*K + k0+tx] = __float2bfloat16(v - __bfloat162float(h));
    }
}

// ---------------- window mean of x (hi+lo, exact routing path) ----------------
__global__ void winmeanx_kernel(){
    int np = blockIdx.x, c = threadIdx.x;
    float s = 0.f;
    #pragma unroll 4
    for (int r = 0; r < 64; r++){
        size_t i = (size_t)(np*64+r)*256 + c;
        s += __bfloat162float(g_ahi[i]) + __bfloat162float(g_alo[i]);
    }
    g_xbar[np*256 + c] = s * (1.f/64.f);
}

// ---------------- q_win/k_win = xbar @ Wq/Wk + b (fp32 exact) ----------------
__global__ void winproj_kernel(const float* __restrict__ qkv_w, const float* __restrict__ qkv_b){
    __shared__ float sx[256];
    int np = blockIdx.x, c = threadIdx.x;
    sx[c] = g_xbar[np*256 + c];
    __syncthreads();
    float qa = qkv_b[c], ka = qkv_b[256 + c];
    #pragma unroll 8
    for (int d = 0; d < 256; d++){
        float xv = sx[d];
        qa += xv * qkv_w[d*768 + c];
        ka += xv * qkv_w[d*768 + 256 + c];
    }
    g_qwin[np*256 + c] = qa;
    g_kwin[np*256 + c] = ka;
}

// ---------------- logits + top-4 (one block per window) ----------------
__global__ void logit_topk_kernel(){
    __shared__ float sq[256];
    __shared__ float sl[64];
    int np = blockIdx.x, n = np / 49;
    int tid = threadIdx.x;
    sq[tid] = g_qwin[np*256 + tid];
    if (tid < 64) sl[tid] = -1e30f;
    __syncthreads();
    int t = tid >> 2, part = tid & 3;
    int tc = (t < 49) ? t : 48;
    const float* kr = &g_kwin[(size_t)(n*49 + tc)*256 + part*64];
    float acc = 0.f;
    #pragma unroll 8
    for (int c = 0; c < 64; c++) acc += sq[part*64 + c] * kr[c];
    acc += __shfl_xor_sync(0xffffffffu, acc, 1);
    acc += __shfl_xor_sync(0xffffffffu, acc, 2);
    if (part == 0 && t < 49) sl[t] = acc * 0.0625f;
    __syncthreads();
    if (tid == 0){
        float bv[4] = {-1e30f,-1e30f,-1e30f,-1e30f};
        int   bi[4] = {0,0,0,0};
        for (int k = 0; k < 49; k++){
            float v = sl[k];
            if (v > bv[3]){
                int pos = 3;
                while (pos > 0 && v > bv[pos-1]) pos--;
                for (int sft = 3; sft > pos; sft--){ bv[sft]=bv[sft-1]; bi[sft]=bi[sft-1]; }
                bv[pos] = v; bi[pos] = k;
            }
        }
        #pragma unroll
        for (int s = 0; s < 4; s++) g_ridx[np*4 + s] = bi[s];
    }
}

// ---------------- lepe: 5x5 depthwise conv on v ----------------
__global__ void lepe_kernel(const float* __restrict__ w, const float* __restrict__ b){
    int pix = blockIdx.x;
    int c = threadIdx.x;
    int n = pix / 3136, r = pix % 3136;
    int y = r / 56, x = r % 56;
    float acc = b[c];
    #pragma unroll
    for (int ky = 0; ky < 5; ky++){
        int yy = y + ky - 2;
        if ((unsigned)yy >= 56u) continue;
        #pragma unroll
        for (int kx = 0; kx < 5; kx++){
            int xx = x + kx - 2;
            if ((unsigned)xx >= 56u) continue;
            int rw = ((n*49 + (yy>>3)*7 + (xx>>3))<<6) + ((yy&7)<<3) + (xx&7);
            acc += g_qkv[(size_t)rw*768 + 512 + c] * w[(ky*5+kx)*256 + c];
        }
    }
    g_lepe[(size_t)img2win(pix)*256 + c] = acc;
}

// ---------------- attention: one block per (window, head) ----------------
// smem: k[256][36] + v[256][36] fp32 = 72KB -> 2+ blocks/SM.
// Scores in registers (64/thread), softmax within quad, probs broadcast via shfl.
__global__ void __launch_bounds__(256) attn_kernel(){
    int np = blockIdx.x;
    int m  = blockIdx.y;
    int n  = np / 49;
    int tid = threadIdx.x;
    extern __shared__ float sm[];
    float* sk = sm;                 // 256*36
    float* sv = sk + 256*36;        // 256*36
    int base = np * 64;

    #pragma unroll
    for (int s4 = 0; s4 < 4; s4++){
        int wsel = g_ridx[np*4 + s4];
        int sb = (n*49 + wsel) * 64;
        for (int idx = tid; idx < 2048; idx += 256){
            int r = idx >> 5, d = idx & 31;
            int kk = s4*64 + r;
            sk[kk*36 + d] = g_qkv[(size_t)(sb+r)*768 + 256 + m*32 + d];
            sv[kk*36 + d] = g_qkv[(size_t)(sb+r)*768 + 512 + m*32 + d];
        }
    }

    int r  = tid >> 2;    // query row 0..63
    int kq = tid & 3;     // quad lane

    // q row straight from gmem into registers (quad-redundant, coalesced per quad)
    float4 qreg[8];
    const float* qrow = &g_qkv[(size_t)(base+r)*768 + m*32];
    #pragma unroll
    for (int u = 0; u < 8; u++) qreg[u] = *(const float4*)(qrow + u*4);
    __syncthreads();

    // scores: thread owns kk = 4*k2 + kq, k2 = 0..63
    float sc[64];
    #pragma unroll
    for (int k2 = 0; k2 < 64; k2++){
        int kk = (k2<<2) + kq;
        float acc = 0.f;
        #pragma unroll
        for (int u = 0; u < 8; u++){
            float4 kv4 = *(float4*)&sk[kk*36 + u*4];
            acc += qreg[u].x*kv4.x + qreg[u].y*kv4.y + qreg[u].z*kv4.z + qreg[u].w*kv4.w;
        }
        sc[k2] = acc * 0.0625f;
    }
    // softmax across quad
    float mx = -1e30f;
    #pragma unroll
    for (int k2 = 0; k2 < 64; k2++) mx = fmaxf(mx, sc[k2]);
    mx = fmaxf(mx, __shfl_xor_sync(0xffffffffu, mx, 1));
    mx = fmaxf(mx, __shfl_xor_sync(0xffffffffu, mx, 2));
    float sum = 0.f;
    #pragma unroll
    for (int k2 = 0; k2 < 64; k2++){
        float e = expf(sc[k2] - mx);
        sc[k2] = e; sum += e;
    }
    sum += __shfl_xor_sync(0xffffffffu, sum, 1);
    sum += __shfl_xor_sync(0xffffffffu, sum, 2);
    float invs = 1.f / sum;
    #pragma unroll
    for (int k2 = 0; k2 < 64; k2++) sc[k2] *= invs;

    // out = aw @ v : thread owns (r, d = kq*8..kq*8+7); probs broadcast within quad
    float oa[8] = {0,0,0,0,0,0,0,0};
    #pragma unroll
    for (int k2 = 0; k2 < 64; k2++){
        #pragma unroll
        for (int qq = 0; qq < 4; qq++){
            float a = __shfl_sync(0xffffffffu, sc[k2], qq, 4);
            int p = (k2<<2) + qq;
            float4 v0 = *(float4*)&sv[p*36 + kq*8];
            float4 v1 = *(float4*)&sv[p*36 + kq*8 + 4];
            oa[0] += a*v0.x; oa[1] += a*v0.y; oa[2] += a*v0.z; oa[3] += a*v0.w;
            oa[4] += a*v1.x; oa[5] += a*v1.y; oa[6] += a*v1.z; oa[7] += a*v1.w;
        }
    }
    #pragma unroll
    for (int j = 0; j < 8; j++)
        g_attn[(size_t)(base+r)*256 + m*32 + kq*8 + j] = oa[j];
}

// ---------------- add attn+lepe, split to bf16 hi/lo ----------------
__global__ void addcvt_kernel(){
    size_t i0 = ((size_t)blockIdx.x*256 + threadIdx.x)*8;
    float4 a0 = *(float4*)&g_attn[i0], a1 = *(float4*)&g_attn[i0+4];
    float4 b0 = *(float4*)&g_lepe[i0], b1 = *(float4*)&g_lepe[i0+4];
    float v[8] = {a0.x+b0.x, a0.y+b0.y, a0.z+b0.z, a0.w+b0.w,
                  a1.x+b1.x, a1.y+b1.y, a1.z+b1.z, a1.w+b1.w};
    uint4 uh, ul;
    split8(v, uh, ul);
    *(uint4*)&g_ahi[i0] = uh;
    *(uint4*)&g_alo[i0] = ul;
}

// ---------------- mma.sync split-bf16 GEMM: 128x128 tile, BK=32, 2-stage cp.async ----
// MODE 0: outf = A@B + bias                       (qkv)
// MODE 1: outf[win2img] = res + A@B + bias        (wo + residual, layout remap)
// MODE 2: outh/outl = split(gelu(A@B + bias))      (mlp1)
// MODE 3: outf = res + A@B + bias                  (mlp2 -> final out)
#define LDH 40   // smem row stride in halves (80B: conflict-free ldmatrix)
template<int MODE>
__global__ void __launch_bounds__(256) mgemm_kernel(
    const __nv_bfloat16* __restrict__ Ahi, const __nv_bfloat16* __restrict__ Alo,
    const __nv_bfloat16* __restrict__ Bhi, const __nv_bfloat16* __restrict__ Blo,
    const float* __restrict__ bias, const float* __restrict__ res,
    float* __restrict__ outf, __nv_bfloat16* __restrict__ outh, __nv_bfloat16* __restrict__ outl,
    int N, int K)
{
    __shared__ __align__(16) __nv_bfloat16 sA[2][128*LDH];
    __shared__ __align__(16) __nv_bfloat16 sB[2][128*LDH];
    const int tid = threadIdx.x, w = tid >> 5, lane = tid & 31;
    const int m0 = blockIdx.y * 128, n0 = blockIdx.x * 128;
    const int wm = (w >> 2) * 64, wn = (w & 3) * 32;
    const int kch = K / 32;
    const int NCH = 3 * kch;

    const uint32_t saA = smem_u32(&sA[0][0]);
    const uint32_t saB = smem_u32(&sB[0][0]);
    const uint32_t STG = 128*LDH*2;

    float acc[4][4][4];
    #pragma unroll
    for (int i = 0; i < 4; i++)
        #pragma unroll
        for (int j = 0; j < 4; j++)
            #pragma unroll
            for (int q = 0; q < 4; q++) acc[i][j][q] = 0.f;

    const int rA = tid >> 2;            // row 0..63 (x2)
    const int sg = (tid & 3) * 8;       // halves offset

    auto issue = [&](int c, int buf){
        int p = c / kch, ko = (c - p*kch) * 32;
        const __nv_bfloat16* Ag = (p == 1) ? Alo : Ahi;
        const __nv_bfloat16* Bg = (p == 2) ? Blo : Bhi;
        uint32_t so0 = (uint32_t)(rA*LDH + sg) * 2 + buf*STG;
        uint32_t so1 = (uint32_t)((64+rA)*LDH + sg) * 2 + buf*STG;
        cp16(saA + so0, Ag + (size_t)(m0+rA)*K + ko + sg);
        cp16(saA + so1, Ag + (size_t)(m0+64+rA)*K + ko + sg);
        cp16(saB + so0, Bg + (size_t)(n0+rA)*K + ko + sg);
        cp16(saB + so1, Bg + (size_t)(n0+64+rA)*K + ko + sg);
        asm volatile("cp.async.commit_group;");
    };

    issue(0, 0);

    for (int c = 0; c < NCH; c++){
        int buf = c & 1;
        if (c + 1 < NCH){
            issue(c+1, buf ^ 1);
            asm volatile("cp.async.wait_group 1;");
        } else {
            asm volatile("cp.async.wait_group 0;");
        }
        __syncthreads();

        #pragma unroll
        for (int ks = 0; ks < 2; ks++){
            const int kk = ks * 16;
            uint32_t afr[4][4], bfr[4][2];
            uint32_t aaddr = saA + buf*STG + (uint32_t)((wm + (lane & 15))*LDH + kk + ((lane >> 4) & 1)*8) * 2;
            #pragma unroll
            for (int mt = 0; mt < 4; mt++)
                ldmA(afr[mt], aaddr + mt*16*LDH*2);
            uint32_t baddr = saB + buf*STG + (uint32_t)((wn + (lane & 7))*LDH + kk + ((lane >> 3) & 1)*8) * 2;
            #pragma unroll
            for (int nt = 0; nt < 4; nt++)
                ldmB(bfr[nt], baddr + nt*8*LDH*2);
            #pragma unroll
            for (int mt = 0; mt < 4; mt++)
                #pragma unroll
                for (int nt = 0; nt < 4; nt++)
                    mma16816(acc[mt][nt], afr[mt], bfr[nt]);
        }
        __syncthreads();
    }

    // epilogue
    #pragma unroll
    for (int mt = 0; mt < 4; mt++){
        int r0 = m0 + wm + mt*16 + (lane >> 2);
        int r1 = r0 + 8;
        int o0 = (MODE == 1) ? win2img(r0) : r0;
        int o1 = (MODE == 1) ? win2img(r1) : r1;
        #pragma unroll
        for (int nt = 0; nt < 4; nt++){
            int col = n0 + wn + nt*8 + (lane & 3)*2;
            float b0 = bias[col], b1 = bias[col+1];
            float v00 = acc[mt][nt][0] + b0, v01 = acc[mt][nt][1] + b1;
            float v10 = acc[mt][nt][2] + b0, v11 = acc[mt][nt][3] + b1;
            if (MODE == 2){
                v00 = 0.5f*v00*(1.f + erff(v00*0.70710678118654752f));
                v01 = 0.5f*v01*(1.f + erff(v01*0.70710678118654752f));
                v10 = 0.5f*v10*(1.f + erff(v10*0.70710678118654752f));
                v11 = 0.5f*v11*(1.f + erff(v11*0.70710678118654752f));
                __nv_bfloat16 h00 = __float2bfloat16(v00), h01 = __float2bfloat16(v01);
                __nv_bfloat16 h10 = __float2bfloat16(v10), h11 = __float2bfloat16(v11);
                *(uint32_t*)&outh[(size_t)o0*N + col] = packbf2(h00, h01);
                *(uint32_t*)&outh[(size_t)o1*N + col] = packbf2(h10, h11);
                *(uint32_t*)&outl[(size_t)o0*N + col] = packbf2(
                    __float2bfloat16(v00 - __bfloat162float(h00)),
                    __float2bfloat16(v01 - __bfloat162float(h01)));
                *(uint32_t*)&outl[(size_t)o1*N + col] = packbf2(
                    __float2bfloat16(v10 - __bfloat162float(h10)),
                    __float2bfloat16(v11 - __bfloat162float(h11)));
            } else {
                if (MODE == 1 || MODE == 3){
                    v00 += res[(size_t)o0*N + col];   v01 += res[(size_t)o0*N + col + 1];
                    v10 += res[(size_t)o1*N + col];   v11 += res[(size_t)o1*N + col + 1];
                }
                *(float2*)&outf[(size_t)o0*N + col] = make_float2(v00, v01);
                *(float2*)&outf[(size_t)o1*N + col] = make_float2(v10, v11);
            }
        }
    }
}

// ---------------- launch ----------------
extern "C" void kernel_launch(void* const* d_in, const int* in_sizes, int n_in,
                              void* d_out, int out_size)
{
    const float* x      = (const float*)d_in[0];
    const float* ln1_g  = (const float*)d_in[1];
    const float* ln1_b  = (const float*)d_in[2];
    const float* qkv_w  = (const float*)d_in[3];
    const float* qkv_b  = (const float*)d_in[4];
    const float* lepe_w = (const float*)d_in[5];
    const float* lepe_b = (const float*)d_in[6];
    const float* wo_w   = (const float*)d_in[7];
    const float* wo_b   = (const float*)d_in[8];
    const float* ln2_g  = (const float*)d_in[9];
    const float* ln2_b  = (const float*)d_in[10];
    const float* mlp_w1 = (const float*)d_in[11];
    const float* mlp_b1 = (const float*)d_in[12];
    const float* mlp_w2 = (const float*)d_in[13];
    const float* mlp_b2 = (const float*)d_in[14];
    float* out = (float*)d_out;

    float *p_qkv, *p_x2;
    __nv_bfloat16 *p_ahi, *p_alo, *p_hhi, *p_hlo, *p_wth, *p_wtl;
    cudaGetSymbolAddress((void**)&p_qkv, g_qkv);
    cudaGetSymbolAddress((void**)&p_x2,  g_x2);
    cudaGetSymbolAddress((void**)&p_ahi, g_ahi);
    cudaGetSymbolAddress((void**)&p_alo, g_alo);
    cudaGetSymbolAddress((void**)&p_hhi, g_hhi);
    cudaGetSymbolAddress((void**)&p_hlo, g_hlo);
    cudaGetSymbolAddress((void**)&p_wth, g_wth);
    cudaGetSymbolAddress((void**)&p_wtl, g_wtl);

    // 0. transpose + split all weights
    wtrans_kernel<<<dim3(768/32, 256/32),  dim3(32,8)>>>(qkv_w,  p_wth+OFF_QKV, p_wtl+OFF_QKV, 256, 768);
    wtrans_kernel<<<dim3(256/32, 256/32),  dim3(32,8)>>>(wo_w,   p_wth+OFF_WO,  p_wtl+OFF_WO,  256, 256);
    wtrans_kernel<<<dim3(1024/32, 256/32), dim3(32,8)>>>(mlp_w1, p_wth+OFF_M1,  p_wtl+OFF_M1,  256, 1024);
    wtrans_kernel<<<dim3(256/32, 1024/32), dim3(32,8)>>>(mlp_w2, p_wth+OFF_M2,  p_wtl+OFF_M2,  1024, 256);
    // 1. LN1 -> window layout, bf16 split
    ln_kernel<true><<<PIX/8, 256>>>(x, ln1_g, ln1_b, p_ahi, p_alo);
    // 2. exact routing path: window means + q/k projection + top-4
    winmeanx_kernel<<<NWIN, 256>>>();
    winproj_kernel<<<NWIN, 256>>>(qkv_w, qkv_b);
    logit_topk_kernel<<<NWIN, 256>>>();
    // 3. qkv GEMM
    mgemm_kernel<0><<<dim3(6, 196), 256>>>(p_ahi, p_alo, p_wth+OFF_QKV, p_wtl+OFF_QKV,
                                           qkv_b, nullptr, p_qkv, nullptr, nullptr, 768, 256);
    // 4. lepe + attention
    lepe_kernel<<<PIX, 256>>>(lepe_w, lepe_b);
    {
        int asmB = 2*256*36*4;   // 72KB
        cudaFuncSetAttribute(attn_kernel, cudaFuncAttributeMaxDynamicSharedMemorySize, asmB);
        attn_kernel<<<dim3(NWIN, 8), 256, asmB>>>();
    }
    // 5. (attn + lepe) -> bf16 split
    addcvt_kernel<<<PIX*256/2048, 256>>>();
    // 6. wo GEMM + residual + layout remap
    mgemm_kernel<1><<<dim3(2, 196), 256>>>(p_ahi, p_alo, p_wth+OFF_WO, p_wtl+OFF_WO,
                                           wo_b, x, p_x2, nullptr, nullptr, 256, 256);
    // 7. LN2 -> bf16 split
    ln_kernel<false><<<PIX/8, 256>>>(p_x2, ln2_g, ln2_b, p_ahi, p_alo);
    // 8. mlp1 + gelu -> bf16 split
    mgemm_kernel<2><<<dim3(8, 196), 256>>>(p_ahi, p_alo, p_wth+OFF_M1, p_wtl+OFF_M1,
                                           mlp_b1, nullptr, nullptr, p_hhi, p_hlo, 1024, 256);
    // 9. mlp2 + residual -> out
    mgemm_kernel<3><<<dim3(2, 196), 256>>>(p_hhi, p_hlo, p_wth+OFF_M2, p_wtl+OFF_M2,
                                           mlp_b2, p_x2, out, nullptr, nullptr, 256, 1024);
}